// round 10
// baseline (speedup 1.0000x reference)
#include <cuda_runtime.h>
#include <cuda_bf16.h>
#include <cstdint>

// Problem constants (fixed by the reference setup)
#define N_NODES   128
#define CAL_N     256
#define N_OBS     64
#define SPB       128    // samples per block in main kernel
#define CHUNK     8      // node-rows per cp.async staging chunk
#define NCHUNK    (N_NODES / CHUNK)   // 16

// Device scratch (allocation-free rule: __device__ globals)
__device__ float4       g_cA[N_NODES];   // {w0, w1, b, sigma} (root: {0,0,0,1})
__device__ uint32_t     g_cPk[N_NODES];  // (p0*SPB*4) | ((p1*SPB*4)<<16); UNSIGNED so
                                         // >>16 is a logical shift (bit31 can be set)
__device__ const float* g_srcP[N_NODES]; // per-node source row: root->rm+i*n else zn+i*n

__device__ __forceinline__ uint32_t smem_u32(const void* p) {
    return (uint32_t)__cvta_generic_to_shared(p);
}

// ---------------------------------------------------------------------------
// K1 (fused cal): 128 blocks x 256 threads. EVERY block redundantly runs the
// noiseless pilot recurrence over [128 nodes][256 samples] in its own smem
// (identical FP ops -> identical result, one wave of 128 blocks), then block
// b rank-counts its own node b and bakes the per-node constants for the main
// pass. Replaces the serial pilot + sigma + g_pilot round-trip.
// jnp.quantile linear: q25 at 63.75 -> v[63]+0.75*(v[64]-v[63]),
//                      q75 at 191.25 -> v[191]+0.25*(v[192]-v[191]).
// ---------------------------------------------------------------------------
__global__ void __launch_bounds__(CAL_N)
cal_kernel(const float* __restrict__ W,
           const float* __restrict__ b,
           const float* __restrict__ pm,
           const int*   __restrict__ pidx,
           const float* __restrict__ root_pilot,
           const float* __restrict__ rm,
           const float* __restrict__ zn,
           int n)
{
    extern __shared__ float xs[];          // [N_NODES][CAL_N] = 128 KB
    __shared__ float4 pc[N_NODES];         // {w0, w1, b, rootFlag}
    __shared__ int    pp[N_NODES];         // p0 | (p1<<8), raw 8-bit ids
    __shared__ float  q[4];

    int node = blockIdx.x;
    int t = threadIdx.x;

    if (t < N_NODES) {
        float m0 = pm[t * 2 + 0], m1 = pm[t * 2 + 1];
        bool  root = (m0 == 0.f) && (m1 == 0.f);
        pc[t] = make_float4(W[t * 2 + 0] * m0, W[t * 2 + 1] * m1,
                            b[t], root ? 1.f : 0.f);
        pp[t] = (pidx[t * 2 + 0] & 0xff) | ((pidx[t * 2 + 1] & 0xff) << 8);
    }
    __syncthreads();

    // Pilot recurrence: thread-private columns, no syncs inside the loop.
    for (int i = 0; i < N_NODES; i++) {
        float4 c  = pc[i];                 // uniform broadcast
        int    pk = pp[i];
        float v;
        if (c.w != 0.f) {                  // uniform branch: root node
            v = root_pilot[i * CAL_N + t];
        } else {
            float pv0 = xs[(pk & 0xff) * CAL_N + t];
            float pv1 = xs[((pk >> 8) & 0xff) * CAL_N + t];
            v = fmaxf(fmaf(c.x, pv0, fmaf(c.y, pv1, c.z)), 0.f);
        }
        xs[i * CAL_N + t] = v;
    }

    // Rank-count this block's node (exact order statistics, stable rank).
    float my = xs[node * CAL_N + t];
    __syncthreads();                       // other threads' columns now visible

    const float* row = xs + node * CAL_N;
    int rank = 0;
    #pragma unroll 8
    for (int j = 0; j < CAL_N; j++) {
        float o = row[j];                  // broadcast read
        rank += (o < my) || (o == my && j < t);   // bijection 0..255
    }
    if (rank == 63)  q[0] = my;
    if (rank == 64)  q[1] = my;
    if (rank == 191) q[2] = my;
    if (rank == 192) q[3] = my;
    __syncthreads();

    if (t == 0) {
        float q25 = q[0] + 0.75f * (q[1] - q[0]);
        float q75 = q[2] + 0.25f * (q[3] - q[2]);
        float sig = 0.1f * fmaxf(q75 - q25, 1e-6f);

        float m0 = pm[node * 2 + 0], m1 = pm[node * 2 + 1];
        bool  root = (m0 == 0.f) && (m1 == 0.f);
        uint32_t p0 = (uint32_t)(pidx[node * 2 + 0] & 0xff) * (SPB * 4);
        uint32_t p1 = (uint32_t)(pidx[node * 2 + 1] & 0xff) * (SPB * 4);
        if (root) {
            g_cA[node]   = make_float4(0.f, 0.f, 0.f, 1.f);
            g_cPk[node]  = 0u;
            g_srcP[node] = rm + (size_t)node * n;
        } else {
            g_cA[node]   = make_float4(W[node * 2 + 0] * m0,
                                       W[node * 2 + 1] * m1,
                                       b[node], sig);
            g_cPk[node]  = p0 | (p1 << 16);
            g_srcP[node] = zn + (size_t)node * n;
        }
    }
}

// ---------------------------------------------------------------------------
// K2: main pass. One sample per thread; node values in shared [node][tid]
// (conflict-free thread-private columns). Noise/root rows are staged through
// a double-buffered smem area via cp.async (LDGSTS): each chunk = 8 node-rows
// x 128 samples (4KB), loaded as 256 x 16B segments by 128 threads while the
// previous chunk is consumed. This pins MLP at the chunk size with ZERO live
// registers (the R3/R8 register ring collapsed to exposed DRAM latency).
//   v_i = relu(w0*pv0 + w1*pv1 + b) + sigma * src_i[s]
// Root: w=b=0, sigma=1 (fmaxf kills 0*garbage NaN) -> v = root_main exactly.
// ---------------------------------------------------------------------------
__global__ void __launch_bounds__(SPB, 3)
main_kernel(const int* __restrict__ chosen,
            float*     __restrict__ out,
            int n)
{
    extern __shared__ float shv[];         // [N_NODES][SPB] (64KB) + stage (8KB)
    float* stage = shv + N_NODES * SPB;    // [2][CHUNK][SPB]
    __shared__ float4       cA[N_NODES];
    __shared__ uint32_t     cPk[N_NODES];
    __shared__ const float* srcP[N_NODES]; // staged pointer table (LDS in prefetch)
    __shared__ int          ch[N_OBS];

    int t  = threadIdx.x;
    int s0 = blockIdx.x * SPB;

    cA[t]   = g_cA[t];
    cPk[t]  = g_cPk[t];
    srcP[t] = g_srcP[t];
    if (t < N_OBS) ch[t] = chosen[t];
    __syncthreads();

    char* myCol = reinterpret_cast<char*>(shv) + t * 4;
    const uint32_t stage_b = smem_u32(stage);

    if (s0 + SPB <= n) {
        // ---- fast path: full block, cp.async double-buffered staging ----
        auto prefetch = [&](int c) {
            int buf = c & 1;
            #pragma unroll
            for (int k = 0; k < 2; k++) {
                int seg   = t + k * SPB;         // 0..255
                int row   = seg >> 5;            // 0..7
                int col16 = seg & 31;            // 16B segment in row
                const float* src = srcP[c * CHUNK + row] + s0 + col16 * 4;
                uint32_t dst = stage_b + (uint32_t)((buf * CHUNK + row) * (SPB * 4)
                                                    + col16 * 16);
                asm volatile("cp.async.cg.shared.global [%0], [%1], 16;\n"
                             :: "r"(dst), "l"(src) : "memory");
            }
            asm volatile("cp.async.commit_group;\n" ::: "memory");
        };

        prefetch(0);
        prefetch(1);

        for (int c = 0; c < NCHUNK; c++) {
            if (c < NCHUNK - 1)
                asm volatile("cp.async.wait_group 1;\n" ::: "memory");
            else
                asm volatile("cp.async.wait_group 0;\n" ::: "memory");
            __syncthreads();               // publish stage chunk c to all warps

            const float* st = stage + (c & 1) * (CHUNK * SPB) + t;
            #pragma unroll
            for (int u = 0; u < CHUNK; u++) {
                int i = c * CHUNK + u;
                float    cur = st[u * SPB];
                float4   cc  = cA[i];                 // uniform LDS.128 broadcast
                uint32_t pk  = cPk[i];
                float pv0 = *reinterpret_cast<float*>(myCol + (pk & 0xffffu));
                float pv1 = *reinterpret_cast<float*>(myCol + (pk >> 16));
                float h   = fmaxf(fmaf(cc.x, pv0, fmaf(cc.y, pv1, cc.z)), 0.f);
                *reinterpret_cast<float*>(myCol + i * (SPB * 4)) = fmaf(cc.w, cur, h);
            }

            if (c + 2 < NCHUNK) {
                __syncthreads();           // all done reading buf (c&1) before reuse
                prefetch(c + 2);
            }
        }

        // Gather chosen nodes, write transposed row [s][0..63] as float4s.
        // Column t of shv was written only by this thread -> no sync needed.
        int s = s0 + t;
        float4* out4 = reinterpret_cast<float4*>(out + (size_t)s * N_OBS);
        #pragma unroll
        for (int j = 0; j < N_OBS / 4; j++) {
            int c0 = ch[4 * j + 0], c1 = ch[4 * j + 1];
            int c2 = ch[4 * j + 2], c3 = ch[4 * j + 3];
            out4[j] = make_float4(shv[c0 * SPB + t], shv[c1 * SPB + t],
                                  shv[c2 * SPB + t], shv[c3 * SPB + t]);
        }
    } else {
        // ---- tail path (unused at n=262144, kept for generality) ----
        int s = s0 + t;
        if (s < n) {
            for (int i = 0; i < N_NODES; i++) {
                float    cur = srcP[i][s];
                float4   cc  = cA[i];
                uint32_t pk  = cPk[i];
                float pv0 = *reinterpret_cast<float*>(myCol + (pk & 0xffffu));
                float pv1 = *reinterpret_cast<float*>(myCol + (pk >> 16));
                float h   = fmaxf(fmaf(cc.x, pv0, fmaf(cc.y, pv1, cc.z)), 0.f);
                *reinterpret_cast<float*>(myCol + i * (SPB * 4)) = fmaf(cc.w, cur, h);
            }
            for (int j = 0; j < N_OBS; j++)
                out[(size_t)s * N_OBS + j] = shv[ch[j] * SPB + t];
        }
    }
}

// ---------------------------------------------------------------------------
// Launch. Input order per setup_inputs dict:
// 0:n_samples 1:W 2:b 3:root_pilot 4:root_main 5:z_noise
// 6:par_mask 7:par_idx 8:is_root 9:chosen
// ---------------------------------------------------------------------------
extern "C" void kernel_launch(void* const* d_in, const int* in_sizes, int n_in,
                              void* d_out, int out_size)
{
    const float* W    = (const float*)d_in[1];
    const float* b    = (const float*)d_in[2];
    const float* rpil = (const float*)d_in[3];
    const float* rm   = (const float*)d_in[4];
    const float* zn   = (const float*)d_in[5];
    const float* pmsk = (const float*)d_in[6];
    const int*   pidx = (const int*)d_in[7];
    const int*   chos = (const int*)d_in[9];
    float*       out  = (float*)d_out;

    int n = in_sizes[4] / N_NODES;     // 262144

    const int calSmem  = N_NODES * CAL_N * sizeof(float);              // 128 KB
    const int mainSmem = (N_NODES * SPB + 2 * CHUNK * SPB) * sizeof(float); // 72 KB

    cudaFuncSetAttribute(cal_kernel,
                         cudaFuncAttributeMaxDynamicSharedMemorySize, calSmem);
    cudaFuncSetAttribute(main_kernel,
                         cudaFuncAttributeMaxDynamicSharedMemorySize, mainSmem);

    cal_kernel<<<N_NODES, CAL_N, calSmem>>>(W, b, pmsk, pidx, rpil, rm, zn, n);

    int grid = (n + SPB - 1) / SPB;    // 2048
    main_kernel<<<grid, SPB, mainSmem>>>(chos, out, n);
}

// round 12
// speedup vs baseline: 1.0974x; 1.0974x over previous
#include <cuda_runtime.h>
#include <cuda_bf16.h>
#include <cstdint>

// Problem constants (fixed by the reference setup)
#define N_NODES   128
#define CAL_N     256
#define N_OBS     64
#define SPB       64     // samples per block in main kernel (2 warps)
#define CHUNK     8      // node-rows per staging chunk
#define NCHUNK    (N_NODES / CHUNK)   // 16
#define DEPTH     4      // cp.async pipeline depth (chunks in flight)

// Device scratch (allocation-free rule: __device__ globals)
__device__ float4       g_cA[N_NODES];   // {w0, w1, b, sigma} (root: {0,0,0,1})
__device__ uint32_t     g_cPk[N_NODES];  // (p0*SPB*4) | ((p1*SPB*4)<<16); UNSIGNED so
                                         // >>16 is a logical shift
__device__ const float* g_srcP[N_NODES]; // per-node source row: root->rm+i*n else zn+i*n

__device__ __forceinline__ uint32_t smem_u32(const void* p) {
    return (uint32_t)__cvta_generic_to_shared(p);
}

// ---------------------------------------------------------------------------
// K1 (fused cal): 128 blocks x 256 threads. EVERY block redundantly runs the
// noiseless pilot recurrence over [128 nodes][256 samples] in its own smem
// (identical FP ops -> identical result), then block b rank-counts its own
// node b and bakes the per-node constants for the main pass.
// jnp.quantile linear: q25 at 63.75 -> v[63]+0.75*(v[64]-v[63]),
//                      q75 at 191.25 -> v[191]+0.25*(v[192]-v[191]).
// ---------------------------------------------------------------------------
__global__ void __launch_bounds__(CAL_N)
cal_kernel(const float* __restrict__ W,
           const float* __restrict__ b,
           const float* __restrict__ pm,
           const int*   __restrict__ pidx,
           const float* __restrict__ root_pilot,
           const float* __restrict__ rm,
           const float* __restrict__ zn,
           int n)
{
    extern __shared__ float xs[];          // [N_NODES][CAL_N] = 128 KB
    __shared__ float4 pc[N_NODES];
    __shared__ int    pp[N_NODES];
    __shared__ float  q[4];

    int node = blockIdx.x;
    int t = threadIdx.x;

    if (t < N_NODES) {
        float m0 = pm[t * 2 + 0], m1 = pm[t * 2 + 1];
        bool  root = (m0 == 0.f) && (m1 == 0.f);
        pc[t] = make_float4(W[t * 2 + 0] * m0, W[t * 2 + 1] * m1,
                            b[t], root ? 1.f : 0.f);
        pp[t] = (pidx[t * 2 + 0] & 0xff) | ((pidx[t * 2 + 1] & 0xff) << 8);
    }
    __syncthreads();

    for (int i = 0; i < N_NODES; i++) {
        float4 c  = pc[i];
        int    pk = pp[i];
        float v;
        if (c.w != 0.f) {
            v = root_pilot[i * CAL_N + t];
        } else {
            float pv0 = xs[(pk & 0xff) * CAL_N + t];
            float pv1 = xs[((pk >> 8) & 0xff) * CAL_N + t];
            v = fmaxf(fmaf(c.x, pv0, fmaf(c.y, pv1, c.z)), 0.f);
        }
        xs[i * CAL_N + t] = v;
    }

    float my = xs[node * CAL_N + t];
    __syncthreads();

    const float* row = xs + node * CAL_N;
    int rank = 0;
    #pragma unroll 8
    for (int j = 0; j < CAL_N; j++) {
        float o = row[j];
        rank += (o < my) || (o == my && j < t);   // stable rank: bijection 0..255
    }
    if (rank == 63)  q[0] = my;
    if (rank == 64)  q[1] = my;
    if (rank == 191) q[2] = my;
    if (rank == 192) q[3] = my;
    __syncthreads();

    if (t == 0) {
        float q25 = q[0] + 0.75f * (q[1] - q[0]);
        float q75 = q[2] + 0.25f * (q[3] - q[2]);
        float sig = 0.1f * fmaxf(q75 - q25, 1e-6f);

        float m0 = pm[node * 2 + 0], m1 = pm[node * 2 + 1];
        bool  root = (m0 == 0.f) && (m1 == 0.f);
        uint32_t p0 = (uint32_t)(pidx[node * 2 + 0] & 0xff) * (SPB * 4);
        uint32_t p1 = (uint32_t)(pidx[node * 2 + 1] & 0xff) * (SPB * 4);
        if (root) {
            g_cA[node]   = make_float4(0.f, 0.f, 0.f, 1.f);
            g_cPk[node]  = 0u;
            g_srcP[node] = rm + (size_t)node * n;
        } else {
            g_cA[node]   = make_float4(W[node * 2 + 0] * m0,
                                       W[node * 2 + 1] * m1,
                                       b[node], sig);
            g_cPk[node]  = p0 | (p1 << 16);
            g_srcP[node] = zn + (size_t)node * n;
        }
    }
}

// ---------------------------------------------------------------------------
// K2: main pass. One sample per thread; node values in shared [node][tid].
// Noise/root rows stream through a 4-deep cp.async pipeline where EACH THREAD
// copies exactly the 4B elements (row, col=t) it will later consume -> stage
// columns are thread-private -> ZERO __syncthreads in the mainloop (the R10
// version lost half its occupancy to smem and serialized on 2 barriers/chunk
// with only 16KB/SM in flight). Here: 5 blocks/SM x 4 chunks x 2KB = 40KB
// outstanding per SM -> DRAM latency covered; 10 warps across 5 independent
// blocks interleave freely.
//   v_i = relu(w0*pv0 + w1*pv1 + b) + sigma * src_i[s]
// Root: w=b=0, sigma=1 (fmaxf kills 0*garbage NaN) -> v = root_main exactly.
// ---------------------------------------------------------------------------
__global__ void __launch_bounds__(SPB)
main_kernel(const int* __restrict__ chosen,
            float*     __restrict__ out,
            int n)
{
    extern __shared__ float shv[];         // [N_NODES][SPB] = 32 KB
    float* stage = shv + N_NODES * SPB;    // [DEPTH][CHUNK][SPB] = 8 KB
    __shared__ float4       cA[N_NODES];
    __shared__ uint32_t     cPk[N_NODES];
    __shared__ const float* srcP[N_NODES];
    __shared__ int          ch[N_OBS];

    int t  = threadIdx.x;
    int s0 = blockIdx.x * SPB;
    int s  = s0 + t;

    #pragma unroll
    for (int j = t; j < N_NODES; j += SPB) {
        cA[j]   = g_cA[j];
        cPk[j]  = g_cPk[j];
        srcP[j] = g_srcP[j];
    }
    ch[t] = chosen[t];                     // N_OBS == SPB
    __syncthreads();                       // the only block-wide sync

    char* myCol = reinterpret_cast<char*>(shv) + t * 4;
    const uint32_t myStage = smem_u32(stage) + (uint32_t)t * 4;

    if (s0 + SPB <= n) {
        // thread-private 4B cp.async: thread t fills column t of each row
        auto prefetch = [&](int c) {
            uint32_t dst = myStage + (uint32_t)(c & (DEPTH - 1)) * (CHUNK * SPB * 4);
            #pragma unroll
            for (int r = 0; r < CHUNK; r++) {
                const float* src = srcP[c * CHUNK + r] + s;   // uniform ptr LDS
                asm volatile("cp.async.ca.shared.global [%0], [%1], 4;\n"
                             :: "r"(dst + r * (SPB * 4)), "l"(src) : "memory");
            }
            asm volatile("cp.async.commit_group;\n" ::: "memory");
        };
        auto consume = [&](int c) {
            const float* st = stage + (c & (DEPTH - 1)) * (CHUNK * SPB) + t;
            #pragma unroll
            for (int u = 0; u < CHUNK; u++) {
                int i = c * CHUNK + u;
                float    cur = st[u * SPB];
                float4   cc  = cA[i];                 // uniform LDS.128 broadcast
                uint32_t pk  = cPk[i];
                float pv0 = *reinterpret_cast<float*>(myCol + (pk & 0xffffu));
                float pv1 = *reinterpret_cast<float*>(myCol + (pk >> 16));  // logical
                float h   = fmaxf(fmaf(cc.x, pv0, fmaf(cc.y, pv1, cc.z)), 0.f);
                *reinterpret_cast<float*>(myCol + i * (SPB * 4)) = fmaf(cc.w, cur, h);
            }
        };

        prefetch(0); prefetch(1); prefetch(2); prefetch(3);

        #pragma unroll 1
        for (int c = 0; c < NCHUNK - DEPTH; c++) {
            asm volatile("cp.async.wait_group %0;\n" :: "n"(DEPTH - 1) : "memory");
            consume(c);
            prefetch(c + DEPTH);
        }
        asm volatile("cp.async.wait_group 2;\n" ::: "memory"); consume(NCHUNK - 4);
        asm volatile("cp.async.wait_group 1;\n" ::: "memory"); consume(NCHUNK - 3);
        asm volatile("cp.async.wait_group 0;\n" ::: "memory");
        consume(NCHUNK - 2); consume(NCHUNK - 1);

        // Gather chosen nodes, write transposed row [s][0..63] as float4s.
        // Column t of shv was written only by this thread -> no sync needed.
        float4* out4 = reinterpret_cast<float4*>(out + (size_t)s * N_OBS);
        #pragma unroll
        for (int j = 0; j < N_OBS / 4; j++) {
            int c0 = ch[4 * j + 0], c1 = ch[4 * j + 1];
            int c2 = ch[4 * j + 2], c3 = ch[4 * j + 3];
            out4[j] = make_float4(shv[c0 * SPB + t], shv[c1 * SPB + t],
                                  shv[c2 * SPB + t], shv[c3 * SPB + t]);
        }
    } else {
        // ---- tail path (unused at n=262144, kept for generality) ----
        if (s < n) {
            for (int i = 0; i < N_NODES; i++) {
                float    cur = srcP[i][s];
                float4   cc  = cA[i];
                uint32_t pk  = cPk[i];
                float pv0 = *reinterpret_cast<float*>(myCol + (pk & 0xffffu));
                float pv1 = *reinterpret_cast<float*>(myCol + (pk >> 16));
                float h   = fmaxf(fmaf(cc.x, pv0, fmaf(cc.y, pv1, cc.z)), 0.f);
                *reinterpret_cast<float*>(myCol + i * (SPB * 4)) = fmaf(cc.w, cur, h);
            }
            for (int j = 0; j < N_OBS; j++)
                out[(size_t)s * N_OBS + j] = shv[ch[j] * SPB + t];
        }
    }
}

// ---------------------------------------------------------------------------
// Launch. Input order per setup_inputs dict:
// 0:n_samples 1:W 2:b 3:root_pilot 4:root_main 5:z_noise
// 6:par_mask 7:par_idx 8:is_root 9:chosen
// ---------------------------------------------------------------------------
extern "C" void kernel_launch(void* const* d_in, const int* in_sizes, int n_in,
                              void* d_out, int out_size)
{
    const float* W    = (const float*)d_in[1];
    const float* b    = (const float*)d_in[2];
    const float* rpil = (const float*)d_in[3];
    const float* rm   = (const float*)d_in[4];
    const float* zn   = (const float*)d_in[5];
    const float* pmsk = (const float*)d_in[6];
    const int*   pidx = (const int*)d_in[7];
    const int*   chos = (const int*)d_in[9];
    float*       out  = (float*)d_out;

    int n = in_sizes[4] / N_NODES;     // 262144

    const int calSmem  = N_NODES * CAL_N * sizeof(float);                    // 128 KB
    const int mainSmem = (N_NODES * SPB + DEPTH * CHUNK * SPB) * sizeof(float); // 40 KB

    cudaFuncSetAttribute(cal_kernel,
                         cudaFuncAttributeMaxDynamicSharedMemorySize, calSmem);

    cal_kernel<<<N_NODES, CAL_N, calSmem>>>(W, b, pmsk, pidx, rpil, rm, zn, n);

    int grid = (n + SPB - 1) / SPB;    // 4096
    main_kernel<<<grid, SPB, mainSmem>>>(chos, out, n);
}